// round 10
// baseline (speedup 1.0000x reference)
#include <cuda_runtime.h>
#include <cuda_fp16.h>
#include <cstdint>

// ---------------------------------------------------------------------------
// Problem constants
// ---------------------------------------------------------------------------
#define KD      128
#define ND      128
#define R_TOTAL (32 * 8192)
#define EPS_F   1e-10f
#define NSM     148
#define NTILES  (R_TOTAL / 128)      // 2048 tiles of 128 rows

// SMEM layout (bytes). Row stride 272 = 256 data + 16 pad.
#define ROWB     272
#define SB_HI    0                       // B = Mt hi (fp16) [128 x 272]
#define SB_LO    34816                   // B = Mt lo (fp16 correction)
#define SA0      69632                   // A buffers (fp16, single part)
#define SA_STRIDE 34816
#define SB2      139264                  // b2, 512 B
#define MB_OFF   139776                  // mbarriers: full0 full1 free0 free1
#define SMEM_TOTAL 139840

#define NTHREADS 384                     // 8 compute warps + 4 producer warps

// ---------------------------------------------------------------------------
// Precomputed small operands
// ---------------------------------------------------------------------------
__device__ __align__(16) float g_b2[ND];
__device__ __align__(16) __half g_Bhi[ND * KD];  // Mt hi: [g][f]
__device__ __align__(16) __half g_Blo[ND * KD];  // Mt lo: [g][f]

// ---------------------------------------------------------------------------
// PTX helpers
// ---------------------------------------------------------------------------
__device__ __forceinline__ uint32_t smem_u32(const void* p) {
    uint32_t a;
    asm("{ .reg .u64 t; cvta.to.shared.u64 t, %1; cvt.u32.u64 %0, t; }" : "=r"(a) : "l"(p));
    return a;
}
#define MBAR_INIT(a, n) asm volatile("mbarrier.init.shared.b64 [%0], %1;" :: "r"(a), "r"(n) : "memory")
#define MBAR_ARRIVE(a)  asm volatile("mbarrier.arrive.release.cta.shared::cta.b64 _, [%0];" :: "r"(a) : "memory")
#define MBAR_WAIT(a, ph) do {                                                     \
    uint32_t _m = (a), _p = (ph);                                                 \
    asm volatile("{\n\t.reg .pred P;\n\tWL_%=:\n\t"                               \
        "mbarrier.try_wait.parity.acquire.cta.shared::cta.b64 P, [%0], %1, 0x989680;\n\t" \
        "@P bra.uni WD_%=;\n\tbra.uni WL_%=;\n\tWD_%=:\n\t}"                      \
        :: "r"(_m), "r"(_p) : "memory");                                          \
} while (0)

#define LDSM_X4(r, a)                                                             \
    asm volatile("ldmatrix.sync.aligned.m8n8.x4.shared.b16 {%0,%1,%2,%3}, [%4];"  \
        : "=r"((r)[0]), "=r"((r)[1]), "=r"((r)[2]), "=r"((r)[3]) : "r"(a))

__device__ __forceinline__ void mma_f16(float* c, const uint32_t* a,
                                        uint32_t b0, uint32_t b1) {
    asm volatile(
        "mma.sync.aligned.m16n8k16.row.col.f32.f16.f16.f32 "
        "{%0,%1,%2,%3}, {%4,%5,%6,%7}, {%8,%9}, {%0,%1,%2,%3};"
        : "+f"(c[0]), "+f"(c[1]), "+f"(c[2]), "+f"(c[3])
        : "r"(a[0]), "r"(a[1]), "r"(a[2]), "r"(a[3]), "r"(b0), "r"(b1));
}

// ---------------------------------------------------------------------------
// Fused prep kernel: 129 blocks x 128 threads.
//   Every block recomputes fac[] into smem (graph is L2-hot, ~2 MB total).
//   Blocks 0-127: M row f -> fp16 hi/lo split (Mt layout [g][f]).
//   Block 128:    b2.
// ---------------------------------------------------------------------------
__global__ void prep_kernel(const float* __restrict__ graph,
                            const float* __restrict__ W,
                            const float* __restrict__ b) {
    __shared__ float sfac[KD];
    int t = threadIdx.x;
    {
        const float* gr = graph + t * ND;
        float s = 0.0f;
        #pragma unroll 8
        for (int j = 0; j < ND; j++) s += gr[j];
        float c = fmaxf(s, EPS_F);
        sfac[t] = (c > EPS_F) ? (1.0f / c) : 0.0f;
    }
    __syncthreads();
    int g = t;
    if (blockIdx.x < KD) {
        int f = blockIdx.x;
        float s = 0.0f;
        #pragma unroll 8
        for (int k = 0; k < KD; k++)
            s = fmaf(W[k * KD + f], graph[k * ND + g] * sfac[k], s);
        __half hi = __float2half(s);
        g_Bhi[g * KD + f] = hi;
        g_Blo[g * KD + f] = __float2half(s - __half2float(hi));
    } else {
        float s2 = 0.0f;
        #pragma unroll 8
        for (int k = 0; k < KD; k++)
            s2 = fmaf(b[k], graph[k * ND + g] * sfac[k], s2);
        g_b2[g] = s2;
    }
}

// ---------------------------------------------------------------------------
// Producer convert+store for one 8-load batch.
// ---------------------------------------------------------------------------
__device__ __forceinline__ void cvt_store8(char* aB, int wt, int phs,
                                           const float4* x) {
    #pragma unroll
    for (int i = 0; i < 8; i++) {
        int v = wt + 128 * (phs * 8 + i);
        int row = v >> 5, cb = (v & 31) * 8;         // 4 fp16 = 8 B
        __half2 p01 = __floats2half2_rn(x[i].x, x[i].y);
        __half2 p23 = __floats2half2_rn(x[i].z, x[i].w);
        *(uint2*)(aB + row * ROWB + cb) =
            make_uint2(*(uint32_t*)&p01, *(uint32_t*)&p23);
    }
}

// ---------------------------------------------------------------------------
// Main persistent kernel.
//   Warps 0-7 : compute; warp w owns rows (w>>1)*32..+32, cols (w&1)*64..+64.
//   Warps 8-11: producer; 8-deep LDG batches, software-pipelined (ping-pong)
//               so DRAM latency is exposed ~once per tile, not 4x.
// ---------------------------------------------------------------------------
__global__ void __launch_bounds__(NTHREADS, 1)
mp_mma_kernel(const float* __restrict__ h, float* __restrict__ out) {
    extern __shared__ char smem[];
    const uint32_t sb = smem_u32(smem);
    const int tid = threadIdx.x, wid = tid >> 5, lane = tid & 31;
    const int bid = blockIdx.x;

    // --- init: B (Mt hi/lo) into padded smem, b2, mbarriers ---
    {
        const uint32_t* bh = (const uint32_t*)g_Bhi;
        const uint32_t* bl = (const uint32_t*)g_Blo;
        for (int w = tid; w < 8192; w += NTHREADS) {     // uint32 index (2 fp16)
            int row = w >> 6, cb = (w & 63) * 4;
            *(uint32_t*)(smem + SB_HI + row * ROWB + cb) = bh[w];
            *(uint32_t*)(smem + SB_LO + row * ROWB + cb) = bl[w];
        }
        if (tid < ND) *(float*)(smem + SB2 + tid * 4) = g_b2[tid];
        if (tid == 0) {
            MBAR_INIT(sb + MB_OFF + 0, 128);   // full[0]  (128 producer threads)
            MBAR_INIT(sb + MB_OFF + 8, 128);   // full[1]
            MBAR_INIT(sb + MB_OFF + 16, 256);  // free[0]  (256 consumer threads)
            MBAR_INIT(sb + MB_OFF + 24, 256);  // free[1]
        }
    }
    __syncthreads();

    const int nt = (NTILES - bid + NSM - 1) / NSM;   // 13 or 14 tiles

    if (wid >= 8) {
        // ========== producer warps (4): pipelined 8-deep batches ==========
        const int wt = tid - 256;
        for (int it = 0; it < nt; ++it) {
            const int p = it & 1, ph = (it >> 1) & 1;
            if (it >= 2) MBAR_WAIT(sb + MB_OFF + 16 + 8 * p, ph ^ 1);
            const float4* hg = (const float4*)h + (size_t)(bid + it * NSM) * 4096;
            char* aB = smem + SA0 + p * SA_STRIDE;
            float4 x[8], y[8];
            #pragma unroll
            for (int i = 0; i < 8; i++) x[i] = hg[wt + 128 * i];
            #pragma unroll
            for (int i = 0; i < 8; i++) y[i] = hg[wt + 128 * (8 + i)];
            cvt_store8(aB, wt, 0, x);
            #pragma unroll
            for (int i = 0; i < 8; i++) x[i] = hg[wt + 128 * (16 + i)];
            cvt_store8(aB, wt, 1, y);
            #pragma unroll
            for (int i = 0; i < 8; i++) y[i] = hg[wt + 128 * (24 + i)];
            cvt_store8(aB, wt, 2, x);
            cvt_store8(aB, wt, 3, y);
            MBAR_ARRIVE(sb + MB_OFF + 8 * p);
        }
    } else {
        // ================= compute warps (8) =================
        const int mrow = (wid >> 1) * 32;            // row quadrant base
        const int ncol = (wid & 1) * 64;             // col quadrant base
        const int lm = lane >> 3, lr = lane & 7;
        const uint32_t aOff = (uint32_t)(((lm & 1) * 8 + lr) * ROWB + (lm >> 1) * 16);
        // X4 B mapping: matrix q -> (nblock q>>1 at +8*ROWB, khalf q&1 at +16B)
        const uint32_t bOff4 = (uint32_t)(lr * ROWB + (lm & 1) * 16 + (lm >> 1) * 8 * ROWB);
        const uint32_t bHiBase = sb + SB_HI + ncol * ROWB + bOff4;
        const uint32_t bLoBase = sb + SB_LO + ncol * ROWB + bOff4;

        for (int it = 0; it < nt; ++it) {
            const int p = it & 1, ph = (it >> 1) & 1;
            MBAR_WAIT(sb + MB_OFF + 8 * p, ph);

            const uint32_t aB = sb + SA0 + p * SA_STRIDE + mrow * ROWB + aOff;

            float acc[2][8][4];
            #pragma unroll
            for (int mt = 0; mt < 2; mt++)
                #pragma unroll
                for (int n = 0; n < 8; n++)
                    #pragma unroll
                    for (int q = 0; q < 4; q++) acc[mt][n][q] = 0.0f;

            #pragma unroll 1
            for (int ks = 0; ks < 8; ks++) {
                const uint32_t koff = ks * 32;       // 16 fp16 = 32 B
                uint32_t a0[4], a1[4];
                LDSM_X4(a0, aB + koff);
                LDSM_X4(a1, aB + 16 * ROWB + koff);
                #pragma unroll
                for (int n4 = 0; n4 < 4; n4++) {
                    uint32_t bh[4], bl[4];
                    LDSM_X4(bh, bHiBase + n4 * 16 * ROWB + koff);
                    LDSM_X4(bl, bLoBase + n4 * 16 * ROWB + koff);
                    mma_f16(acc[0][2 * n4 + 0], a0, bh[0], bh[1]);
                    mma_f16(acc[1][2 * n4 + 0], a1, bh[0], bh[1]);
                    mma_f16(acc[0][2 * n4 + 1], a0, bh[2], bh[3]);
                    mma_f16(acc[1][2 * n4 + 1], a1, bh[2], bh[3]);
                    mma_f16(acc[0][2 * n4 + 0], a0, bl[0], bl[1]);
                    mma_f16(acc[1][2 * n4 + 0], a1, bl[0], bl[1]);
                    mma_f16(acc[0][2 * n4 + 1], a0, bl[2], bl[3]);
                    mma_f16(acc[1][2 * n4 + 1], a1, bl[2], bl[3]);
                }
            }
            MBAR_ARRIVE(sb + MB_OFF + 16 + 8 * p);   // buffer free (results in regs)

            // epilogue: + b2, direct STG
            float2 bb[8];
            #pragma unroll
            for (int n = 0; n < 8; n++)
                bb[n] = *(const float2*)(smem + SB2 + (ncol + n * 8 + (lane & 3) * 2) * 4);
            const size_t tile = (size_t)(bid + it * NSM);
            #pragma unroll
            for (int mt = 0; mt < 2; mt++) {
                size_t r0 = tile * 128 + mrow + mt * 16 + (lane >> 2);
                float* o = out + r0 * ND + ncol + (lane & 3) * 2;
                #pragma unroll
                for (int n = 0; n < 8; n++) {
                    *(float2*)(o + n * 8) =
                        make_float2(acc[mt][n][0] + bb[n].x, acc[mt][n][1] + bb[n].y);
                    *(float2*)(o + 8 * ND + n * 8) =
                        make_float2(acc[mt][n][2] + bb[n].x, acc[mt][n][3] + bb[n].y);
                }
            }
        }
    }
}

// ---------------------------------------------------------------------------
// Launch
// ---------------------------------------------------------------------------
extern "C" void kernel_launch(void* const* d_in, const int* in_sizes, int n_in,
                              void* d_out, int out_size) {
    (void)in_sizes; (void)n_in; (void)out_size;
    const float* h     = (const float*)d_in[0];
    const float* graph = (const float*)d_in[1];
    const float* W     = (const float*)d_in[2];
    const float* b     = (const float*)d_in[3];
    float* out         = (float*)d_out;

    cudaFuncSetAttribute(mp_mma_kernel,
                         cudaFuncAttributeMaxDynamicSharedMemorySize, SMEM_TOTAL);

    prep_kernel<<<KD + 1, KD>>>(graph, W, b);
    mp_mma_kernel<<<NSM, NTHREADS, SMEM_TOTAL>>>(h, out);
}